// round 2
// baseline (speedup 1.0000x reference)
#include <cuda_runtime.h>
#include <cuda_bf16.h>

// Problem constants (from reference)
#define GX 352
#define GY 400
#define GZ 1
#define BSZ 4
#define NSEG (BSZ * GZ * GY * GX)   // 563200
#define NPTS 2000000
#define CH 4

// Output layout: [ mean: NSEG*4 f32 ][ counts: NSEG f32 ]

__global__ void __launch_bounds__(256)
scatter_kernel(const float4* __restrict__ feats,
               const int4* __restrict__ coors,
               float4* __restrict__ sums,
               float* __restrict__ counts) {
    // 4 points per thread, front-batched loads for MLP
    int t = blockIdx.x * blockDim.x + threadIdx.x;
    int base = t * 4;
    if (base >= NPTS) return;

    int4  c[4];
    float4 f[4];
#pragma unroll
    for (int k = 0; k < 4; k++) {
        int idx = base + k;
        if (idx < NPTS) {
            c[k] = __ldcs(&coors[idx]);   // evict-first: don't pollute L2
            f[k] = __ldcs(&feats[idx]);
        }
    }
#pragma unroll
    for (int k = 0; k < 4; k++) {
        int idx = base + k;
        if (idx < NPTS) {
            // seg = ((b*GZ + z)*GY + y)*GX + x
            int seg = ((c[k].x * GZ + c[k].y) * GY + c[k].z) * GX + c[k].w;
            atomicAdd(&sums[seg], f[k]);      // RED.128 to L2
            atomicAdd(&counts[seg], 1.0f);    // RED.32 to L2
        }
    }
}

__global__ void __launch_bounds__(256)
finalize_kernel(float4* __restrict__ sums,
                const float* __restrict__ counts) {
    int s = blockIdx.x * blockDim.x + threadIdx.x;
    if (s >= NSEG) return;
    float cnt = counts[s];
    float inv = 1.0f / fmaxf(cnt, 1.0f);
    float4 v = sums[s];
    v.x *= inv; v.y *= inv; v.z *= inv; v.w *= inv;
    sums[s] = v;                  // in-place: sums -> mean
}

extern "C" void kernel_launch(void* const* d_in, const int* in_sizes, int n_in,
                              void* d_out, int out_size) {
    const float4* feats = (const float4*)d_in[0];   // (NPTS, 4) f32
    const int4*   coors = (const int4*)d_in[1];     // (NPTS, 4) i32
    float* out = (float*)d_out;

    float4* sums   = (float4*)out;                   // NSEG float4
    float*  counts = out + (size_t)NSEG * CH;        // NSEG floats

    // 1) zero the whole output via driver memset (graph-capturable memset node)
    cudaMemsetAsync(out, 0, (size_t)(NSEG * CH + NSEG) * sizeof(float));

    // 2) scatter-add features and counts (4 points/thread)
    {
        int threads = 256;
        int nthreads_needed = (NPTS + 3) / 4;
        int blocks = (nthreads_needed + threads - 1) / threads;
        scatter_kernel<<<blocks, threads>>>(feats, coors, sums, counts);
    }

    // 3) divide sums by max(count,1) in place
    {
        int threads = 256;
        int blocks = (NSEG + threads - 1) / threads;
        finalize_kernel<<<blocks, threads>>>(sums, counts);
    }
}

// round 3
// speedup vs baseline: 1.0778x; 1.0778x over previous
#include <cuda_runtime.h>
#include <cuda_bf16.h>

// Problem constants (from reference)
#define GX 352
#define GY 400
#define GZ 1
#define BSZ 4
#define NSEG (BSZ * GZ * GY * GX)   // 563200
#define NPTS 2000000
#define CH 4

// Output layout: [ mean: NSEG*4 f32 ][ counts: NSEG f32 ]

__global__ void __launch_bounds__(256)
scatter_kernel(const float4* __restrict__ feats,
               const int4* __restrict__ coors,
               float4* __restrict__ sums,
               float* __restrict__ counts) {
    int i = blockIdx.x * blockDim.x + threadIdx.x;
    if (i >= NPTS) return;
    int4 c = coors[i];            // b, z, y, x
    int seg = ((c.x * GZ + c.y) * GY + c.z) * GX + c.w;
    float4 f = feats[i];
    atomicAdd(&sums[seg], f);     // RED.128 (fire-and-forget)
    atomicAdd(&counts[seg], 1.0f);// RED.32
}

// 4 segments per thread; NSEG = 563200 divisible by 4 -> no bounds checks.
__global__ void __launch_bounds__(256)
finalize_kernel(float4* __restrict__ sums,
                const float4* __restrict__ counts4) {
    int t = blockIdx.x * blockDim.x + threadIdx.x;
    if (t >= NSEG / 4) return;

    // One vector load gets 4 counts; 4 vector loads get the sums.
    float4 cnt = counts4[t];
    int base = t * 4;
    float4 v0 = sums[base + 0];
    float4 v1 = sums[base + 1];
    float4 v2 = sums[base + 2];
    float4 v3 = sums[base + 3];

    float i0 = 1.0f / fmaxf(cnt.x, 1.0f);
    float i1 = 1.0f / fmaxf(cnt.y, 1.0f);
    float i2 = 1.0f / fmaxf(cnt.z, 1.0f);
    float i3 = 1.0f / fmaxf(cnt.w, 1.0f);

    v0.x *= i0; v0.y *= i0; v0.z *= i0; v0.w *= i0;
    v1.x *= i1; v1.y *= i1; v1.z *= i1; v1.w *= i1;
    v2.x *= i2; v2.y *= i2; v2.z *= i2; v2.w *= i2;
    v3.x *= i3; v3.y *= i3; v3.z *= i3; v3.w *= i3;

    sums[base + 0] = v0;
    sums[base + 1] = v1;
    sums[base + 2] = v2;
    sums[base + 3] = v3;
}

extern "C" void kernel_launch(void* const* d_in, const int* in_sizes, int n_in,
                              void* d_out, int out_size) {
    const float4* feats = (const float4*)d_in[0];   // (NPTS, 4) f32
    const int4*   coors = (const int4*)d_in[1];     // (NPTS, 4) i32
    float* out = (float*)d_out;

    float4* sums   = (float4*)out;                   // NSEG float4
    float*  counts = out + (size_t)NSEG * CH;        // NSEG floats

    // 1) zero the whole output (graph-capturable memset node)
    cudaMemsetAsync(out, 0, (size_t)(NSEG * CH + NSEG) * sizeof(float));

    // 2) scatter-add features and counts (1 point/thread)
    {
        int threads = 256;
        int blocks = (NPTS + threads - 1) / threads;
        scatter_kernel<<<blocks, threads>>>(feats, coors, sums, counts);
    }

    // 3) divide sums by max(count,1) in place (4 segs/thread, vectorized)
    {
        int threads = 256;
        int nthreads_needed = NSEG / 4;              // 140800
        int blocks = (nthreads_needed + threads - 1) / threads;
        finalize_kernel<<<blocks, threads>>>(sums, (const float4*)counts);
    }
}